// round 11
// baseline (speedup 1.0000x reference)
#include <cuda_runtime.h>
#include <cuda_fp16.h>
#include <cstdint>

#define NN 50000
#define NPAD 50048
#define EE 800000
#define FIN 128
#define HID 32
#define NHEADS 8
#define H1 256
#define NUM_WALKS 512
#define WALK_LEN 64
#define WINDOW 5
#define NEG_S 10
#define NEG_SLOPE 0.2f
#define INV_TEMP (1.0f/0.07f)

// ---------------- scratch (device globals; no cudaMalloc allowed) ----------
__device__ __half g_xh[(size_t)NPAD * FIN];
__device__ __half g_w1t[256 * FIN];
__device__ __half g_w2t[256 * H1];
__device__ __half g_xw1h[(size_t)NPAD * H1];
__device__ __half g_xw2h[(size_t)NPAD * H1];
__device__ __half g_e1h[(size_t)NPAD * H1];
__device__ __half g_e2h[(size_t)NN * H1];
__device__ float g_als1[(size_t)NPAD * NHEADS];
__device__ float g_ald1[(size_t)NPAD * NHEADS];
__device__ float g_als2[NN];
__device__ float g_ald2[NN];
__device__ float g_alpS[8 * NPAD];
__device__ float g_alpD[8 * NPAD];
__device__ float g_ss1[NN];
__device__ float g_inv[NN];
__device__ int   g_deg[NN];
__device__ int   g_rowptr[NN + 1];
__device__ int   g_wptr[NN];
__device__ int   g_col[EE];
__device__ float g_terms[NUM_WALKS];
__device__ unsigned g_done;

// ---------------- PTX helpers (arch-generic sm_80+) ------------------------
__device__ __forceinline__ uint32_t smem_u32(const void* p) {
    uint32_t a;
    asm("{ .reg .u64 t; cvta.to.shared.u64 t, %1; cvt.u32.u64 %0, t; }" : "=r"(a) : "l"(p));
    return a;
}
#define CP16(SADDR, GPTR) \
    asm volatile("cp.async.cg.shared.global [%0], [%1], 16;" :: "r"(SADDR), "l"(GPTR))
#define CP_COMMIT() asm volatile("cp.async.commit_group;" ::: "memory")
#define CP_WAIT(N)  asm volatile("cp.async.wait_group %0;" :: "n"(N) : "memory")
#define LDSM4(R, ADDR) \
    asm volatile("ldmatrix.sync.aligned.m8n8.x4.shared.b16 {%0,%1,%2,%3}, [%4];" \
        : "=r"((R)[0]), "=r"((R)[1]), "=r"((R)[2]), "=r"((R)[3]) : "r"(ADDR))
#define MMAF16(C, A, B0, B1) \
    asm volatile("mma.sync.aligned.m16n8k16.row.col.f32.f16.f16.f32 " \
        "{%0,%1,%2,%3}, {%4,%5,%6,%7}, {%8,%9}, {%0,%1,%2,%3};" \
        : "+f"((C)[0]), "+f"((C)[1]), "+f"((C)[2]), "+f"((C)[3]) \
        : "r"((A)[0]), "r"((A)[1]), "r"((A)[2]), "r"((A)[3]), "r"(B0), "r"(B1))

__device__ __forceinline__ void h8_to_f8(const uint4& r, float* f) {
    const __half2* hp = reinterpret_cast<const __half2*>(&r);
#pragma unroll
    for (int i = 0; i < 4; i++) {
        float2 t = __half22float2(hp[i]);
        f[2 * i] = t.x; f[2 * i + 1] = t.y;
    }
}

// ---------------- CSR build ------------------------------------------------
__global__ void k_count(const int* __restrict__ edge_index) {
    int e = blockIdx.x * blockDim.x + threadIdx.x;
    if (e < EE) atomicAdd(&g_deg[edge_index[EE + e]], 1);
}

__global__ void k_scan() {
    __shared__ int wsums[32];
    __shared__ int carry_s;
    int tid = threadIdx.x, lane = tid & 31, w = tid >> 5;
    if (tid == 0) carry_s = 0;
    __syncthreads();
    for (int base = 0; base < NN; base += 4096) {
        int i0 = base + tid * 4;
        int v[4];
        if (i0 + 4 <= NN) {
            int4 q = *(const int4*)(g_deg + i0);
            v[0] = q.x; v[1] = q.y; v[2] = q.z; v[3] = q.w;
        } else {
#pragma unroll
            for (int j = 0; j < 4; j++) v[j] = (i0 + j < NN) ? g_deg[i0 + j] : 0;
        }
        int tsum = v[0] + v[1] + v[2] + v[3];
        int inc = tsum;
#pragma unroll
        for (int o = 1; o < 32; o <<= 1) {
            int t = __shfl_up_sync(0xffffffffu, inc, o);
            if (lane >= o) inc += t;
        }
        if (lane == 31) wsums[w] = inc;
        __syncthreads();
        if (w == 0) {
            int ws = wsums[lane];
#pragma unroll
            for (int o = 1; o < 32; o <<= 1) {
                int t = __shfl_up_sync(0xffffffffu, ws, o);
                if (lane >= o) ws += t;
            }
            wsums[lane] = ws;
        }
        __syncthreads();
        int offset = carry_s + (w ? wsums[w - 1] : 0) + inc - tsum;
        int e0 = offset, e1 = e0 + v[0], e2 = e1 + v[1], e3 = e2 + v[2];
        if (i0 < NN)     { g_rowptr[i0]     = e0; g_wptr[i0]     = e0; }
        if (i0 + 1 < NN) { g_rowptr[i0 + 1] = e1; g_wptr[i0 + 1] = e1; }
        if (i0 + 2 < NN) { g_rowptr[i0 + 2] = e2; g_wptr[i0 + 2] = e2; }
        if (i0 + 3 < NN) { g_rowptr[i0 + 3] = e3; g_wptr[i0 + 3] = e3; }
        __syncthreads();
        if (tid == 1023) carry_s = offset + tsum;
        __syncthreads();
    }
    if (tid == 0) g_rowptr[NN] = carry_s;
}

__global__ void k_scatter(const int* __restrict__ edge_index) {
    int e = blockIdx.x * blockDim.x + threadIdx.x;
    if (e < EE) {
        int src = edge_index[e];
        int dst = edge_index[EE + e];
        g_col[atomicAdd(&g_wptr[dst], 1)] = src;
    }
}

// ---------------- fused fp16 prep: x cvt + W1t + W2t -----------------------
#define NXCHUNK (NPAD * FIN / 4)
__global__ void k_prep(const float* __restrict__ x, const float* __restrict__ W1f,
                       const float* __restrict__ W2f)
{
    int t = blockIdx.x * blockDim.x + threadIdx.x;
    if (t < NXCHUNK) {
        int base = t * 4;
        int row = base >> 7;
        float4 v = (row < NN) ? *(const float4*)(x + base) : make_float4(0.f, 0.f, 0.f, 0.f);
        __half2 h0 = __floats2half2_rn(v.x, v.y);
        __half2 h1 = __floats2half2_rn(v.z, v.w);
        *(uint2*)(g_xh + base) = make_uint2(*(unsigned*)&h0, *(unsigned*)&h1);
    } else {
        int u = t - NXCHUNK;
        if (u < 256 * FIN) {
            int n = u / FIN, k = u - n * FIN;
            g_w1t[u] = __float2half_rn(W1f[k * 256 + n]);
        } else if (u < 256 * FIN + 256 * H1) {
            int v2 = u - 256 * FIN;
            int n = v2 / H1, k = v2 - n * H1;
            g_w2t[v2] = __float2half_rn(W2f[k * 256 + n]);
        }
    }
}

// ---------------- fp16 HMMA GEMM, fp16 C, fused al epilogue ----------------
#define MBUF 10240
#define MSTAGE (2 * MBUF)
#define MSM_TOTAL (2 * MSTAGE)

__device__ __forceinline__ void stage_chunk(
    uint32_t sb32, int rbase, int nbase, int k0, int K, int tid,
    const __half* __restrict__ A, const __half* __restrict__ B)
{
#pragma unroll
    for (int t = tid; t < 512; t += 256) {
        int r = t >> 2, seg = t & 3;
        uint32_t so = sb32 + r * 80 + seg * 16;
        CP16(so,        A + (size_t)(rbase + r) * K + k0 + seg * 8);
        CP16(so + MBUF, B + (size_t)(nbase + r) * K + k0 + seg * 8);
    }
}

template<int FOLD>
__global__ __launch_bounds__(256)
void k_mmagemm(const __half* __restrict__ A, const __half* __restrict__ B,
               __half* __restrict__ C, int K,
               const float* __restrict__ avs, const float* __restrict__ avd,
               float* __restrict__ foldS, float* __restrict__ foldD)
{
    extern __shared__ char sm[];
    uint32_t smb = smem_u32(sm);
    int tid = threadIdx.x, lane = tid & 31, wid = tid >> 5;
    int rbase = blockIdx.x * 128, nbase = blockIdx.y * 128;
    int wm = (wid >> 2) * 64, wn = (wid & 3) * 32;

    float acc[4][4][4];
#pragma unroll
    for (int i = 0; i < 4; i++)
#pragma unroll
        for (int j = 0; j < 4; j++)
#pragma unroll
            for (int q = 0; q < 4; q++) acc[i][j][q] = 0.f;

    int nch = K >> 5;
    stage_chunk(smb, rbase, nbase, 0, K, tid, A, B);
    CP_COMMIT();

    int row = lane & 15, kh = lane >> 4;
    for (int ch = 0; ch < nch; ch++) {
        if (ch + 1 < nch) {
            stage_chunk(smb + ((ch + 1) & 1) * MSTAGE, rbase, nbase, (ch + 1) << 5, K, tid, A, B);
            CP_COMMIT();
            CP_WAIT(1);
        } else {
            CP_WAIT(0);
        }
        __syncthreads();

        uint32_t s0 = smb + (ch & 1) * MSTAGE;
#pragma unroll
        for (int s = 0; s < 2; s++) {
            int colb = (s * 16 + kh * 8) * 2;
            uint32_t ah[4][4], bh[2][4];
#pragma unroll
            for (int mi = 0; mi < 4; mi++)
                LDSM4(ah[mi], s0 + (wm + mi * 16 + row) * 80 + colb);
#pragma unroll
            for (int bi = 0; bi < 2; bi++)
                LDSM4(bh[bi], s0 + MBUF + (wn + bi * 16 + row) * 80 + colb);
#pragma unroll
            for (int mi = 0; mi < 4; mi++)
#pragma unroll
                for (int ni = 0; ni < 4; ni++) {
                    int bi = ni >> 1, hf = ni & 1;
                    MMAF16(acc[mi][ni], ah[mi], bh[bi][hf], bh[bi][hf + 2]);
                }
        }
        __syncthreads();
    }

#pragma unroll
    for (int mi = 0; mi < 4; mi++)
#pragma unroll
        for (int ni = 0; ni < 4; ni++) {
            int r0 = rbase + wm + mi * 16 + (lane >> 2);
            int c  = nbase + wn + ni * 8 + (lane & 3) * 2;
            __half* p = C + (size_t)r0 * 256 + c;
            *(__half2*)p = __floats2half2_rn(acc[mi][ni][0], acc[mi][ni][1]);
            *(__half2*)(p + 8 * 256) = __floats2half2_rn(acc[mi][ni][2], acc[mi][ni][3]);
        }

    // fused attention-logit fold
    {
        int h = (nbase + wn) >> 5;
        int slot = blockIdx.y * 4 + (wid & 3);
#pragma unroll
        for (int mi = 0; mi < 4; mi++) {
            float ps0 = 0.f, ps1 = 0.f, pd0 = 0.f, pd1 = 0.f;
#pragma unroll
            for (int ni = 0; ni < 4; ni++) {
                int cc = ni * 8 + (lane & 3) * 2;
                float s0, s1, d0, d1;
                if (FOLD == 1) {
                    s0 = avs[h * 32 + cc]; s1 = avs[h * 32 + cc + 1];
                    d0 = avd[h * 32 + cc]; d1 = avd[h * 32 + cc + 1];
                } else {
                    int c = nbase + wn + cc;
                    s0 = avs[c]; s1 = avs[c + 1];
                    d0 = avd[c]; d1 = avd[c + 1];
                }
                ps0 += acc[mi][ni][0] * s0 + acc[mi][ni][1] * s1;
                ps1 += acc[mi][ni][2] * s0 + acc[mi][ni][3] * s1;
                pd0 += acc[mi][ni][0] * d0 + acc[mi][ni][1] * d1;
                pd1 += acc[mi][ni][2] * d0 + acc[mi][ni][3] * d1;
            }
#pragma unroll
            for (int o = 1; o <= 2; o <<= 1) {
                ps0 += __shfl_xor_sync(0xffffffffu, ps0, o);
                ps1 += __shfl_xor_sync(0xffffffffu, ps1, o);
                pd0 += __shfl_xor_sync(0xffffffffu, pd0, o);
                pd1 += __shfl_xor_sync(0xffffffffu, pd1, o);
            }
            if ((lane & 3) == 0) {
                int r0 = rbase + wm + mi * 16 + (lane >> 2);
                if (FOLD == 1) {
                    foldS[(size_t)r0 * 8 + h] = ps0;
                    foldS[(size_t)(r0 + 8) * 8 + h] = ps1;
                    foldD[(size_t)r0 * 8 + h] = pd0;
                    foldD[(size_t)(r0 + 8) * 8 + h] = pd1;
                } else {
                    foldS[(size_t)slot * NPAD + r0] = ps0;
                    foldS[(size_t)slot * NPAD + r0 + 8] = ps1;
                    foldD[(size_t)slot * NPAD + r0] = pd0;
                    foldD[(size_t)slot * NPAD + r0 + 8] = pd1;
                }
            }
        }
    }
}

// sum the 8 layer-2 al partial slots (deterministic)
__global__ void k_alsum2()
{
    int i = blockIdx.x * blockDim.x + threadIdx.x;
    if (i >= NN) return;
    float s = 0.f, d = 0.f;
#pragma unroll
    for (int k = 0; k < 8; k++) {
        s += g_alpS[(size_t)k * NPAD + i];
        d += g_alpD[(size_t)k * NPAD + i];
    }
    g_als2[i] = s;
    g_ald2[i] = d;
}

// ---------------- warp-per-node softmax aggregation ------------------------
// Lane-parallel exponent precompute per 32-edge chunk; weighted loop is
// shfl + row-gather + FMA only (high MLP).
template<int H, bool ELU, bool FININV>
__global__ __launch_bounds__(256)
void k_agg_w(const __half* __restrict__ xw, const float* __restrict__ als,
             const float* __restrict__ ald, const float* __restrict__ bias,
             __half* __restrict__ outh, float* __restrict__ ssout)
{
    int gw = (blockIdx.x * blockDim.x + threadIdx.x) >> 5;
    int lane = threadIdx.x & 31;
    if (gw >= NN) return;
    int n = gw;
    int beg = g_rowptr[n];
    int deg = g_rowptr[n + 1] - beg;

    const int myh = (H == 8) ? (lane >> 2) : 0;
    const float admy = ald[(size_t)n * H + myh];

    float eself = als[(size_t)n * H + myh] + admy;
    eself = eself > 0.f ? eself : NEG_SLOPE * eself;
    float exs = __expf(eself);
    float denp = 0.f;

    float acc[8];
    {
        uint4 raw = *(const uint4*)(xw + (size_t)n * 256 + (lane << 3));
        float f[8]; h8_to_f8(raw, f);
#pragma unroll
        for (int t = 0; t < 8; t++) acc[t] = exs * f[t];
    }

    for (int base = 0; base < deg; base += 32) {
        int idx = base + lane;
        int scol = (idx < deg) ? g_col[beg + idx] : 0;
        int cn = min(32, deg - base);

        if (H == 8) {
            // lane (h=lane>>2, r=lane&3) computes ex for edges j=4q+r, head h
            float exv[8];
#pragma unroll
            for (int q = 0; q < 8; q++) {
                int j = (q << 2) | (lane & 3);
                int sj = __shfl_sync(0xffffffffu, scol, j);
                float ex = 0.f;
                if (j < cn) {
                    float e = als[(size_t)sj * 8 + myh] + admy;
                    e = e > 0.f ? e : NEG_SLOPE * e;
                    ex = __expf(e);
                }
                exv[q] = ex;
                denp += ex;
            }
#pragma unroll
            for (int q = 0; q < 8; q++) {
                float exq = exv[q];
#pragma unroll 4
                for (int r = 0; r < 4; r++) {
                    int jj = (q << 2) | r;
                    if (jj < cn) {
                        int s = __shfl_sync(0xffffffffu, scol, jj);
                        float exj = __shfl_sync(0xffffffffu, exq, r, 4);
                        uint4 raw = *(const uint4*)(xw + (size_t)s * 256 + (lane << 3));
                        float f[8]; h8_to_f8(raw, f);
#pragma unroll
                        for (int t = 0; t < 8; t++) acc[t] += exj * f[t];
                    }
                }
            }
        } else {
            float exl = 0.f;
            if (lane < cn) {
                float e = als[scol] + admy;
                e = e > 0.f ? e : NEG_SLOPE * e;
                exl = __expf(e);
            }
            denp += exl;
#pragma unroll 4
            for (int jj = 0; jj < cn; jj++) {
                int s = __shfl_sync(0xffffffffu, scol, jj);
                float exj = __shfl_sync(0xffffffffu, exl, jj);
                uint4 raw = *(const uint4*)(xw + (size_t)s * 256 + (lane << 3));
                float f[8]; h8_to_f8(raw, f);
#pragma unroll
                for (int t = 0; t < 8; t++) acc[t] += exj * f[t];
            }
        }
    }

    float den;
    if (H == 8) {
        denp += __shfl_xor_sync(0xffffffffu, denp, 1);
        denp += __shfl_xor_sync(0xffffffffu, denp, 2);
        den = denp + exs;
    } else {
#pragma unroll
        for (int o = 16; o; o >>= 1) denp += __shfl_xor_sync(0xffffffffu, denp, o);
        den = denp + exs;
    }

    float invd = 1.f / den;
    const float4* bb = (const float4*)(bias + (lane << 3));
    float4 b0 = bb[0], b1 = bb[1];
    float o[8];
    o[0] = acc[0] * invd + b0.x; o[1] = acc[1] * invd + b0.y;
    o[2] = acc[2] * invd + b0.z; o[3] = acc[3] * invd + b0.w;
    o[4] = acc[4] * invd + b1.x; o[5] = acc[5] * invd + b1.y;
    o[6] = acc[6] * invd + b1.z; o[7] = acc[7] * invd + b1.w;
    float ssq = 0.f;
#pragma unroll
    for (int t = 0; t < 8; t++) {
        if (ELU) o[t] = o[t] > 0.f ? o[t] : expm1f(o[t]);
        ssq += o[t] * o[t];
    }
    {
        uint4 ho;
        __half2* hp = (__half2*)&ho;
        hp[0] = __floats2half2_rn(o[0], o[1]);
        hp[1] = __floats2half2_rn(o[2], o[3]);
        hp[2] = __floats2half2_rn(o[4], o[5]);
        hp[3] = __floats2half2_rn(o[6], o[7]);
        *(uint4*)(outh + (size_t)n * 256 + (lane << 3)) = ho;
    }
#pragma unroll
    for (int oo = 16; oo; oo >>= 1) ssq += __shfl_xor_sync(0xffffffffu, ssq, oo);
    if (lane == 0) {
        if (FININV) g_inv[n] = 1.f / fmaxf(sqrtf(ssout[n] + ssq), 1e-8f);
        else        ssout[n] = ssq;
    }
}

// ---------------- contrastive loss: block per walk + last-block reduce -----
#define SMEM_EMB_F4 (WALK_LEN * 128)
#define SMEM_LOSS_BYTES (SMEM_EMB_F4 * 16 + WALK_LEN * 4 + WALK_LEN * 4 + 16 * 4)

__device__ __forceinline__ float dot16(const float4& a0, const float4& a1,
                                       const float4& a2, const float4& a3,
                                       const float4& p0, const float4& p1,
                                       const float4& p2, const float4& p3)
{
    float s = a0.x * p0.x + a0.y * p0.y + a0.z * p0.z + a0.w * p0.w
            + a1.x * p1.x + a1.y * p1.y + a1.z * p1.z + a1.w * p1.w
            + a2.x * p2.x + a2.y * p2.y + a2.z * p2.z + a2.w * p2.w
            + a3.x * p3.x + a3.y * p3.y + a3.z * p3.z + a3.w * p3.w;
#pragma unroll
    for (int o = 16; o; o >>= 1) s += __shfl_xor_sync(0xffffffffu, s, o);
    return s;
}
__device__ __forceinline__ float4 h4_to_f4(uint2 r) {
    const __half2* hp = reinterpret_cast<const __half2*>(&r);
    float2 a = __half22float2(hp[0]), b = __half22float2(hp[1]);
    return make_float4(a.x, a.y, b.x, b.y);
}

__global__ __launch_bounds__(512)
void k_loss(const int* __restrict__ walks, const int* __restrict__ negs,
            float* __restrict__ out)
{
    extern __shared__ char smraw[];
    float4* sm4   = (float4*)smraw;
    int*    ids_s = (int*)(smraw + SMEM_EMB_F4 * 16);
    float*  inv_s = (float*)(smraw + SMEM_EMB_F4 * 16 + WALK_LEN * 4);
    float*  wsum  = (float*)(smraw + SMEM_EMB_F4 * 16 + WALK_LEN * 8);
    __shared__ int s_last;

    int b = blockIdx.x;
    int tid = threadIdx.x, lane = tid & 31, w = tid >> 5;

    if (tid < WALK_LEN) {
        int id = walks[b * WALK_LEN + tid];
        ids_s[tid] = id;
        inv_s[tid] = g_inv[id];
    }
    __syncthreads();

    for (int f = tid; f < WALK_LEN * 64; f += 512) {
        int r = f >> 6, q = f & 63;
        int id = ids_s[r];
        float iv = inv_s[r];
        uint4 raw = (q < 32) ? *(const uint4*)(g_e1h + (size_t)id * 256 + q * 8)
                             : *(const uint4*)(g_e2h + (size_t)id * 256 + (q - 32) * 8);
        float fv[8]; h8_to_f8(raw, fv);
        sm4[r * 128 + 2 * q]     = make_float4(fv[0] * iv, fv[1] * iv, fv[2] * iv, fv[3] * iv);
        sm4[r * 128 + 2 * q + 1] = make_float4(fv[4] * iv, fv[5] * iv, fv[6] * iv, fv[7] * iv);
    }
    __syncthreads();

    float term_acc = 0.f;
    for (int k = 0; k < 4; k++) {
        int l = (w << 2) | k;
        const float4* ar = sm4 + (size_t)l * 128;
        float4 A0 = ar[lane], A1 = ar[32 + lane], A2 = ar[64 + lane], A3 = ar[96 + lane];

        int posid[2 * WINDOW];
        bool pval[2 * WINDOW];
        float pos_sum = 0.f;
#pragma unroll
        for (int p = 0; p < 2 * WINDOW; p++) {
            int off = (p < WINDOW) ? (p - WINDOW) : (p - WINDOW + 1);
            int pp = l + off;
            bool val = (pp >= 0) && (pp < WALK_LEN);
            int ppc = min(max(pp, 0), WALK_LEN - 1);
            pval[p] = val;
            posid[p] = ids_s[ppc];
            const float4* pr = sm4 + (size_t)ppc * 128;
            float4 P0 = pr[lane], P1 = pr[32 + lane], P2 = pr[64 + lane], P3 = pr[96 + lane];
            float d = dot16(A0, A1, A2, A3, P0, P1, P2, P3);
            if (val) pos_sum += __expf(d * INV_TEMP);
        }

        int nbase = (b * WALK_LEN + l) * NEG_S;
        int ngl = (lane < NEG_S) ? negs[nbase + lane] : 0;
        float invn = (lane < NEG_S) ? g_inv[ngl] : 0.f;

        // batched partial dots: all 40 row-loads in flight, no reduce inside
        float pd[NEG_S];
#pragma unroll
        for (int s = 0; s < NEG_S; s++) {
            int ng = __shfl_sync(0xffffffffu, ngl, s);
            const __half* n1 = g_e1h + (size_t)ng * 256;
            const __half* n2 = g_e2h + (size_t)ng * 256;
            float4 P0 = h4_to_f4(*(const uint2*)(n1 + 4 * lane));
            float4 P1 = h4_to_f4(*(const uint2*)(n1 + 128 + 4 * lane));
            float4 P2 = h4_to_f4(*(const uint2*)(n2 + 4 * lane));
            float4 P3 = h4_to_f4(*(const uint2*)(n2 + 128 + 4 * lane));
            pd[s] = A0.x * P0.x + A0.y * P0.y + A0.z * P0.z + A0.w * P0.w
                  + A1.x * P1.x + A1.y * P1.y + A1.z * P1.z + A1.w * P1.w
                  + A2.x * P2.x + A2.y * P2.y + A2.z * P2.z + A2.w * P2.w
                  + A3.x * P3.x + A3.y * P3.y + A3.z * P3.z + A3.w * P3.w;
        }
        float neg_sum = 0.f;
#pragma unroll
        for (int s = 0; s < NEG_S; s++) {
            float d = pd[s];
#pragma unroll
            for (int o = 16; o; o >>= 1) d += __shfl_xor_sync(0xffffffffu, d, o);
            int ng = __shfl_sync(0xffffffffu, ngl, s);
            float iv = __shfl_sync(0xffffffffu, invn, s);
            bool inpos = false;
#pragma unroll
            for (int p = 0; p < 2 * WINDOW; p++)
                inpos = inpos || (pval[p] && (ng == posid[p]));
            float sim = d * iv * INV_TEMP;
            if (!inpos) neg_sum += __expf(sim);
        }
        term_acc += log1pf(neg_sum / pos_sum);
    }

    if (lane == 0) wsum[w] = term_acc;
    __syncthreads();
    if (w == 0) {
        float s = (lane < 16) ? wsum[lane] : 0.f;
#pragma unroll
        for (int o = 16; o; o >>= 1) s += __shfl_xor_sync(0xffffffffu, s, o);
        if (lane == 0) g_terms[b] = s;
    }

    // last-block deterministic reduction (ticket self-resets for graph replay)
    if (tid == 0) {
        __threadfence();
        unsigned t = atomicAdd(&g_done, 1u);
        s_last = (t == NUM_WALKS - 1);
    }
    __syncthreads();
    if (s_last) {
        __threadfence();
        float v = g_terms[tid];
        __syncthreads();
        __shared__ float red[512];
        red[tid] = v;
        __syncthreads();
        for (int o = 256; o; o >>= 1) {
            if (tid < o) red[tid] += red[tid + o];
            __syncthreads();
        }
        if (tid == 0) { out[0] = red[0]; g_done = 0; }
    }
}

// ---------------- driver ---------------------------------------------------
extern "C" void kernel_launch(void* const* d_in, const int* in_sizes, int n_in,
                              void* d_out, int out_size)
{
    const float* x          = (const float*)d_in[0];
    const int*   edge_index = (const int*)  d_in[1];
    const int*   walks      = (const int*)  d_in[2];
    const int*   negs       = (const int*)  d_in[3];
    const float* W1         = (const float*)d_in[4];
    const float* a_src1     = (const float*)d_in[5];
    const float* a_dst1     = (const float*)d_in[6];
    const float* b1         = (const float*)d_in[7];
    const float* W2         = (const float*)d_in[8];
    const float* a_src2     = (const float*)d_in[9];
    const float* a_dst2     = (const float*)d_in[10];
    const float* b2         = (const float*)d_in[11];
    float* out = (float*)d_out;

    float *als1, *ald1, *als2, *ald2, *ss1, *alpS, *alpD;
    __half *xh, *w1t, *w2t, *xw1h, *xw2h, *e1h, *e2h;
    void* degp;
    cudaGetSymbolAddress((void**)&xh,   g_xh);
    cudaGetSymbolAddress((void**)&w1t,  g_w1t);
    cudaGetSymbolAddress((void**)&w2t,  g_w2t);
    cudaGetSymbolAddress((void**)&xw1h, g_xw1h);
    cudaGetSymbolAddress((void**)&xw2h, g_xw2h);
    cudaGetSymbolAddress((void**)&e1h,  g_e1h);
    cudaGetSymbolAddress((void**)&e2h,  g_e2h);
    cudaGetSymbolAddress((void**)&als1, g_als1);
    cudaGetSymbolAddress((void**)&ald1, g_ald1);
    cudaGetSymbolAddress((void**)&als2, g_als2);
    cudaGetSymbolAddress((void**)&ald2, g_ald2);
    cudaGetSymbolAddress((void**)&alpS, g_alpS);
    cudaGetSymbolAddress((void**)&alpD, g_alpD);
    cudaGetSymbolAddress((void**)&ss1,  g_ss1);
    cudaGetSymbolAddress(&degp, g_deg);

    static cudaStream_t s2 = nullptr;
    static cudaEvent_t evF = nullptr, evJ = nullptr;
    static int attr_set = 0;
    if (!attr_set) {
        cudaFuncSetAttribute(k_loss, cudaFuncAttributeMaxDynamicSharedMemorySize,
                             SMEM_LOSS_BYTES);
        cudaFuncSetAttribute(k_mmagemm<1>, cudaFuncAttributeMaxDynamicSharedMemorySize,
                             MSM_TOTAL);
        cudaFuncSetAttribute(k_mmagemm<2>, cudaFuncAttributeMaxDynamicSharedMemorySize,
                             MSM_TOTAL);
        cudaStreamCreateWithFlags(&s2, cudaStreamNonBlocking);
        cudaEventCreateWithFlags(&evF, cudaEventDisableTiming);
        cudaEventCreateWithFlags(&evJ, cudaEventDisableTiming);
        attr_set = 1;
    }

    // ---- fork: CSR build on s2, prep + GEMM1 on main stream ---------------
    cudaEventRecord(evF, 0);
    cudaStreamWaitEvent(s2, evF, 0);

    cudaMemsetAsync(degp, 0, NN * sizeof(int), s2);
    k_count<<<(EE + 255) / 256, 256, 0, s2>>>(edge_index);
    k_scan<<<1, 1024, 0, s2>>>();
    k_scatter<<<(EE + 255) / 256, 256, 0, s2>>>(edge_index);
    cudaEventRecord(evJ, s2);

    k_prep<<<(NXCHUNK + 256 * (FIN + H1) + 255) / 256, 256>>>(x, W1, W2);
    k_mmagemm<1><<<dim3(NPAD / 128, 2), 256, MSM_TOTAL>>>(
        xh, w1t, xw1h, FIN, a_src1, a_dst1, als1, ald1);

    // ---- join --------------------------------------------------------------
    cudaStreamWaitEvent(0, evJ, 0);

    // layer 1 aggregation (emb1 -> e1h, also GEMM2's A operand)
    k_agg_w<NHEADS, true, false><<<(NN * 32 + 255) / 256, 256>>>(
        xw1h, als1, ald1, b1, e1h, ss1);

    // layer 2
    k_mmagemm<2><<<dim3(NPAD / 128, 2), 256, MSM_TOTAL>>>(
        e1h, w2t, xw2h, H1, a_src2, a_dst2, alpS, alpD);
    k_alsum2<<<(NN + 255) / 256, 256>>>();
    k_agg_w<1, false, true><<<(NN * 32 + 255) / 256, 256>>>(
        xw2h, als2, ald2, b2, e2h, ss1);

    // loss (+ fused final reduction)
    k_loss<<<NUM_WALKS, 512, SMEM_LOSS_BYTES>>>(walks, negs, out);
}

// round 14
// speedup vs baseline: 1.0066x; 1.0066x over previous
#include <cuda_runtime.h>
#include <cuda_fp16.h>
#include <cstdint>

#define NN 50000
#define NPAD 50048
#define EE 800000
#define FIN 128
#define HID 32
#define NHEADS 8
#define H1 256
#define NUM_WALKS 512
#define WALK_LEN 64
#define WINDOW 5
#define NEG_S 10
#define NEG_SLOPE 0.2f
#define INV_TEMP (1.0f/0.07f)

// ---------------- scratch (device globals; no cudaMalloc allowed) ----------
__device__ __half g_xh[(size_t)NPAD * FIN];
__device__ __half g_w1t[256 * FIN];
__device__ __half g_w2t[256 * H1];
__device__ __half g_xw1h[(size_t)NPAD * H1];
__device__ __half g_xw2h[(size_t)NPAD * H1];
__device__ __half g_e1h[(size_t)NPAD * H1];
__device__ __half g_e2h[(size_t)NN * H1];
__device__ float g_als1[(size_t)NPAD * NHEADS];
__device__ float g_ald1[(size_t)NPAD * NHEADS];
__device__ float g_als2[NN];
__device__ float g_ald2[NN];
__device__ float g_alpS[8 * NPAD];
__device__ float g_alpD[8 * NPAD];
__device__ float g_ss1[NN];
__device__ float g_inv[NN];
__device__ int   g_deg[NN];
__device__ int   g_rowptr[NN + 1];
__device__ int   g_wptr[NN];
__device__ int   g_col[EE];
__device__ float g_terms[NUM_WALKS];
__device__ unsigned g_done;

// ---------------- PTX helpers (arch-generic sm_80+) ------------------------
__device__ __forceinline__ uint32_t smem_u32(const void* p) {
    uint32_t a;
    asm("{ .reg .u64 t; cvta.to.shared.u64 t, %1; cvt.u32.u64 %0, t; }" : "=r"(a) : "l"(p));
    return a;
}
#define CP16(SADDR, GPTR) \
    asm volatile("cp.async.cg.shared.global [%0], [%1], 16;" :: "r"(SADDR), "l"(GPTR))
#define CP_COMMIT() asm volatile("cp.async.commit_group;" ::: "memory")
#define CP_WAIT(N)  asm volatile("cp.async.wait_group %0;" :: "n"(N) : "memory")
#define LDSM4(R, ADDR) \
    asm volatile("ldmatrix.sync.aligned.m8n8.x4.shared.b16 {%0,%1,%2,%3}, [%4];" \
        : "=r"((R)[0]), "=r"((R)[1]), "=r"((R)[2]), "=r"((R)[3]) : "r"(ADDR))
#define MMAF16(C, A, B0, B1) \
    asm volatile("mma.sync.aligned.m16n8k16.row.col.f32.f16.f16.f32 " \
        "{%0,%1,%2,%3}, {%4,%5,%6,%7}, {%8,%9}, {%0,%1,%2,%3};" \
        : "+f"((C)[0]), "+f"((C)[1]), "+f"((C)[2]), "+f"((C)[3]) \
        : "r"((A)[0]), "r"((A)[1]), "r"((A)[2]), "r"((A)[3]), "r"(B0), "r"(B1))

__device__ __forceinline__ void h8_to_f8(const uint4& r, float* f) {
    const __half2* hp = reinterpret_cast<const __half2*>(&r);
#pragma unroll
    for (int i = 0; i < 4; i++) {
        float2 t = __half22float2(hp[i]);
        f[2 * i] = t.x; f[2 * i + 1] = t.y;
    }
}

// ---------------- CSR build ------------------------------------------------
__global__ void k_count(const int* __restrict__ edge_index) {
    int e = blockIdx.x * blockDim.x + threadIdx.x;
    if (e < EE) atomicAdd(&g_deg[edge_index[EE + e]], 1);
}

__global__ void k_scan() {
    __shared__ int wsums[32];
    __shared__ int carry_s;
    int tid = threadIdx.x, lane = tid & 31, w = tid >> 5;
    if (tid == 0) carry_s = 0;
    __syncthreads();
    for (int base = 0; base < NN; base += 4096) {
        int i0 = base + tid * 4;
        int v[4];
        if (i0 + 4 <= NN) {
            int4 q = *(const int4*)(g_deg + i0);
            v[0] = q.x; v[1] = q.y; v[2] = q.z; v[3] = q.w;
        } else {
#pragma unroll
            for (int j = 0; j < 4; j++) v[j] = (i0 + j < NN) ? g_deg[i0 + j] : 0;
        }
        int tsum = v[0] + v[1] + v[2] + v[3];
        int inc = tsum;
#pragma unroll
        for (int o = 1; o < 32; o <<= 1) {
            int t = __shfl_up_sync(0xffffffffu, inc, o);
            if (lane >= o) inc += t;
        }
        if (lane == 31) wsums[w] = inc;
        __syncthreads();
        if (w == 0) {
            int ws = wsums[lane];
#pragma unroll
            for (int o = 1; o < 32; o <<= 1) {
                int t = __shfl_up_sync(0xffffffffu, ws, o);
                if (lane >= o) ws += t;
            }
            wsums[lane] = ws;
        }
        __syncthreads();
        int offset = carry_s + (w ? wsums[w - 1] : 0) + inc - tsum;
        int e0 = offset, e1 = e0 + v[0], e2 = e1 + v[1], e3 = e2 + v[2];
        if (i0 < NN)     { g_rowptr[i0]     = e0; g_wptr[i0]     = e0; }
        if (i0 + 1 < NN) { g_rowptr[i0 + 1] = e1; g_wptr[i0 + 1] = e1; }
        if (i0 + 2 < NN) { g_rowptr[i0 + 2] = e2; g_wptr[i0 + 2] = e2; }
        if (i0 + 3 < NN) { g_rowptr[i0 + 3] = e3; g_wptr[i0 + 3] = e3; }
        __syncthreads();
        if (tid == 1023) carry_s = offset + tsum;
        __syncthreads();
    }
    if (tid == 0) g_rowptr[NN] = carry_s;
}

__global__ void k_scatter(const int* __restrict__ edge_index) {
    int e = blockIdx.x * blockDim.x + threadIdx.x;
    if (e < EE) {
        int src = edge_index[e];
        int dst = edge_index[EE + e];
        g_col[atomicAdd(&g_wptr[dst], 1)] = src;
    }
}

// ---------------- fp16 prep ------------------------------------------------
#define NXCHUNK (NPAD * FIN / 4)
__global__ void k_prepX(const float* __restrict__ x)
{
    int t = blockIdx.x * blockDim.x + threadIdx.x;
    if (t >= NXCHUNK) return;
    int base = t * 4;
    int row = base >> 7;
    float4 v = (row < NN) ? *(const float4*)(x + base) : make_float4(0.f, 0.f, 0.f, 0.f);
    __half2 h0 = __floats2half2_rn(v.x, v.y);
    __half2 h1 = __floats2half2_rn(v.z, v.w);
    *(uint2*)(g_xh + base) = make_uint2(*(unsigned*)&h0, *(unsigned*)&h1);
}

// coalesced tiled transpose: W[K][256] (fp32) -> Wt[256][K] (fp16)
__global__ void k_prepW(const float* __restrict__ W, __half* __restrict__ Wt, int K)
{
    __shared__ float tile[32][33];
    int bx = blockIdx.x * 32;              // n base
    int by = blockIdx.y * 32;              // k base
    int tx = threadIdx.x, ty = threadIdx.y; // 32 x 8
#pragma unroll
    for (int i = 0; i < 4; i++)
        tile[ty + i * 8][tx] = W[(size_t)(by + ty + i * 8) * 256 + bx + tx];
    __syncthreads();
#pragma unroll
    for (int i = 0; i < 4; i++)
        Wt[(size_t)(bx + ty + i * 8) * K + by + tx] = __float2half_rn(tile[tx][ty + i * 8]);
}

// ---------------- fp16 HMMA GEMM, fp16 C, fused al epilogue ----------------
#define MBUF 10240
#define MSTAGE (2 * MBUF)
#define MSM_TOTAL (2 * MSTAGE)

__device__ __forceinline__ void stage_chunk(
    uint32_t sb32, int rbase, int nbase, int k0, int K, int tid,
    const __half* __restrict__ A, const __half* __restrict__ B)
{
#pragma unroll
    for (int t = tid; t < 512; t += 256) {
        int r = t >> 2, seg = t & 3;
        uint32_t so = sb32 + r * 80 + seg * 16;
        CP16(so,        A + (size_t)(rbase + r) * K + k0 + seg * 8);
        CP16(so + MBUF, B + (size_t)(nbase + r) * K + k0 + seg * 8);
    }
}

template<int FOLD>
__global__ __launch_bounds__(256)
void k_mmagemm(const __half* __restrict__ A, const __half* __restrict__ B,
               __half* __restrict__ C, int K,
               const float* __restrict__ avs, const float* __restrict__ avd,
               float* __restrict__ foldS, float* __restrict__ foldD)
{
    extern __shared__ char sm[];
    uint32_t smb = smem_u32(sm);
    int tid = threadIdx.x, lane = tid & 31, wid = tid >> 5;
    int rbase = blockIdx.x * 128, nbase = blockIdx.y * 128;
    int wm = (wid >> 2) * 64, wn = (wid & 3) * 32;

    float acc[4][4][4];
#pragma unroll
    for (int i = 0; i < 4; i++)
#pragma unroll
        for (int j = 0; j < 4; j++)
#pragma unroll
            for (int q = 0; q < 4; q++) acc[i][j][q] = 0.f;

    int nch = K >> 5;
    stage_chunk(smb, rbase, nbase, 0, K, tid, A, B);
    CP_COMMIT();

    int row = lane & 15, kh = lane >> 4;
    for (int ch = 0; ch < nch; ch++) {
        if (ch + 1 < nch) {
            stage_chunk(smb + ((ch + 1) & 1) * MSTAGE, rbase, nbase, (ch + 1) << 5, K, tid, A, B);
            CP_COMMIT();
            CP_WAIT(1);
        } else {
            CP_WAIT(0);
        }
        __syncthreads();

        uint32_t s0 = smb + (ch & 1) * MSTAGE;
#pragma unroll
        for (int s = 0; s < 2; s++) {
            int colb = (s * 16 + kh * 8) * 2;
            uint32_t ah[4][4], bh[2][4];
#pragma unroll
            for (int mi = 0; mi < 4; mi++)
                LDSM4(ah[mi], s0 + (wm + mi * 16 + row) * 80 + colb);
#pragma unroll
            for (int bi = 0; bi < 2; bi++)
                LDSM4(bh[bi], s0 + MBUF + (wn + bi * 16 + row) * 80 + colb);
#pragma unroll
            for (int mi = 0; mi < 4; mi++)
#pragma unroll
                for (int ni = 0; ni < 4; ni++) {
                    int bi = ni >> 1, hf = ni & 1;
                    MMAF16(acc[mi][ni], ah[mi], bh[bi][hf], bh[bi][hf + 2]);
                }
        }
        __syncthreads();
    }

#pragma unroll
    for (int mi = 0; mi < 4; mi++)
#pragma unroll
        for (int ni = 0; ni < 4; ni++) {
            int r0 = rbase + wm + mi * 16 + (lane >> 2);
            int c  = nbase + wn + ni * 8 + (lane & 3) * 2;
            __half* p = C + (size_t)r0 * 256 + c;
            *(__half2*)p = __floats2half2_rn(acc[mi][ni][0], acc[mi][ni][1]);
            *(__half2*)(p + 8 * 256) = __floats2half2_rn(acc[mi][ni][2], acc[mi][ni][3]);
        }

    // fused attention-logit fold
    {
        int h = (nbase + wn) >> 5;
        int slot = blockIdx.y * 4 + (wid & 3);
#pragma unroll
        for (int mi = 0; mi < 4; mi++) {
            float ps0 = 0.f, ps1 = 0.f, pd0 = 0.f, pd1 = 0.f;
#pragma unroll
            for (int ni = 0; ni < 4; ni++) {
                int cc = ni * 8 + (lane & 3) * 2;
                float s0, s1, d0, d1;
                if (FOLD == 1) {
                    s0 = avs[h * 32 + cc]; s1 = avs[h * 32 + cc + 1];
                    d0 = avd[h * 32 + cc]; d1 = avd[h * 32 + cc + 1];
                } else {
                    int c = nbase + wn + cc;
                    s0 = avs[c]; s1 = avs[c + 1];
                    d0 = avd[c]; d1 = avd[c + 1];
                }
                ps0 += acc[mi][ni][0] * s0 + acc[mi][ni][1] * s1;
                ps1 += acc[mi][ni][2] * s0 + acc[mi][ni][3] * s1;
                pd0 += acc[mi][ni][0] * d0 + acc[mi][ni][1] * d1;
                pd1 += acc[mi][ni][2] * d0 + acc[mi][ni][3] * d1;
            }
#pragma unroll
            for (int o = 1; o <= 2; o <<= 1) {
                ps0 += __shfl_xor_sync(0xffffffffu, ps0, o);
                ps1 += __shfl_xor_sync(0xffffffffu, ps1, o);
                pd0 += __shfl_xor_sync(0xffffffffu, pd0, o);
                pd1 += __shfl_xor_sync(0xffffffffu, pd1, o);
            }
            if ((lane & 3) == 0) {
                int r0 = rbase + wm + mi * 16 + (lane >> 2);
                if (FOLD == 1) {
                    foldS[(size_t)r0 * 8 + h] = ps0;
                    foldS[(size_t)(r0 + 8) * 8 + h] = ps1;
                    foldD[(size_t)r0 * 8 + h] = pd0;
                    foldD[(size_t)(r0 + 8) * 8 + h] = pd1;
                } else {
                    foldS[(size_t)slot * NPAD + r0] = ps0;
                    foldS[(size_t)slot * NPAD + r0 + 8] = ps1;
                    foldD[(size_t)slot * NPAD + r0] = pd0;
                    foldD[(size_t)slot * NPAD + r0 + 8] = pd1;
                }
            }
        }
    }
}

// sum the 8 layer-2 al partial slots (deterministic)
__global__ void k_alsum2()
{
    int i = blockIdx.x * blockDim.x + threadIdx.x;
    if (i >= NN) return;
    float s = 0.f, d = 0.f;
#pragma unroll
    for (int k = 0; k < 8; k++) {
        s += g_alpS[(size_t)k * NPAD + i];
        d += g_alpD[(size_t)k * NPAD + i];
    }
    g_als2[i] = s;
    g_ald2[i] = d;
}

// ---------------- warp-per-node softmax aggregation (R10 version) ----------
template<int H, bool ELU, bool FININV>
__global__ __launch_bounds__(256)
void k_agg_w(const __half* __restrict__ xw, const float* __restrict__ als,
             const float* __restrict__ ald, const float* __restrict__ bias,
             __half* __restrict__ outh, float* __restrict__ ssout)
{
    int gw = (blockIdx.x * blockDim.x + threadIdx.x) >> 5;
    int lane = threadIdx.x & 31;
    if (gw >= NN) return;
    int n = gw;
    int beg = g_rowptr[n];
    int deg = g_rowptr[n + 1] - beg;

    const int myh = (H == 8) ? (lane >> 2) : 0;
    const float admy = ald[(size_t)n * H + myh];

    float eself = als[(size_t)n * H + myh] + admy;
    eself = eself > 0.f ? eself : NEG_SLOPE * eself;
    float exs = __expf(eself);
    float den = exs;

    float acc[8];
    {
        uint4 raw = *(const uint4*)(xw + (size_t)n * 256 + (lane << 3));
        float f[8]; h8_to_f8(raw, f);
#pragma unroll
        for (int t = 0; t < 8; t++) acc[t] = exs * f[t];
    }

    for (int base = 0; base < deg; base += 32) {
        int idx = base + lane;
        int scol = (idx < deg) ? g_col[beg + idx] : 0;
        int cn = min(32, deg - base);
#pragma unroll 4
        for (int jj = 0; jj < cn; jj++) {
            int s = __shfl_sync(0xffffffffu, scol, jj);
            float e = als[(size_t)s * H + myh] + admy;
            e = e > 0.f ? e : NEG_SLOPE * e;
            float ex = __expf(e);
            den += ex;
            uint4 raw = *(const uint4*)(xw + (size_t)s * 256 + (lane << 3));
            float f[8]; h8_to_f8(raw, f);
#pragma unroll
            for (int t = 0; t < 8; t++) acc[t] += ex * f[t];
        }
    }

    float invd = 1.f / den;
    const float4* bb = (const float4*)(bias + (lane << 3));
    float4 b0 = bb[0], b1 = bb[1];
    float o[8];
    o[0] = acc[0] * invd + b0.x; o[1] = acc[1] * invd + b0.y;
    o[2] = acc[2] * invd + b0.z; o[3] = acc[3] * invd + b0.w;
    o[4] = acc[4] * invd + b1.x; o[5] = acc[5] * invd + b1.y;
    o[6] = acc[6] * invd + b1.z; o[7] = acc[7] * invd + b1.w;
    float ssq = 0.f;
#pragma unroll
    for (int t = 0; t < 8; t++) {
        if (ELU) o[t] = o[t] > 0.f ? o[t] : expm1f(o[t]);
        ssq += o[t] * o[t];
    }
    {
        uint4 ho;
        __half2* hp = (__half2*)&ho;
        hp[0] = __floats2half2_rn(o[0], o[1]);
        hp[1] = __floats2half2_rn(o[2], o[3]);
        hp[2] = __floats2half2_rn(o[4], o[5]);
        hp[3] = __floats2half2_rn(o[6], o[7]);
        *(uint4*)(outh + (size_t)n * 256 + (lane << 3)) = ho;
    }
#pragma unroll
    for (int oo = 16; oo; oo >>= 1) ssq += __shfl_xor_sync(0xffffffffu, ssq, oo);
    if (lane == 0) {
        if (FININV) g_inv[n] = 1.f / fmaxf(sqrtf(ssout[n] + ssq), 1e-8f);
        else        ssout[n] = ssq;
    }
}

// ---------------- contrastive loss: block per walk + last-block reduce -----
#define SMEM_EMB_F4 (WALK_LEN * 128)
#define SMEM_LOSS_BYTES (SMEM_EMB_F4 * 16 + WALK_LEN * 4 + WALK_LEN * 4 + 16 * 4)

__device__ __forceinline__ float dot16(const float4& a0, const float4& a1,
                                       const float4& a2, const float4& a3,
                                       const float4& p0, const float4& p1,
                                       const float4& p2, const float4& p3)
{
    float s = a0.x * p0.x + a0.y * p0.y + a0.z * p0.z + a0.w * p0.w
            + a1.x * p1.x + a1.y * p1.y + a1.z * p1.z + a1.w * p1.w
            + a2.x * p2.x + a2.y * p2.y + a2.z * p2.z + a2.w * p2.w
            + a3.x * p3.x + a3.y * p3.y + a3.z * p3.z + a3.w * p3.w;
#pragma unroll
    for (int o = 16; o; o >>= 1) s += __shfl_xor_sync(0xffffffffu, s, o);
    return s;
}
__device__ __forceinline__ float4 h4_to_f4(uint2 r) {
    const __half2* hp = reinterpret_cast<const __half2*>(&r);
    float2 a = __half22float2(hp[0]), b = __half22float2(hp[1]);
    return make_float4(a.x, a.y, b.x, b.y);
}

__global__ __launch_bounds__(512)
void k_loss(const int* __restrict__ walks, const int* __restrict__ negs,
            float* __restrict__ out)
{
    extern __shared__ char smraw[];
    float4* sm4   = (float4*)smraw;
    int*    ids_s = (int*)(smraw + SMEM_EMB_F4 * 16);
    float*  inv_s = (float*)(smraw + SMEM_EMB_F4 * 16 + WALK_LEN * 4);
    float*  wsum  = (float*)(smraw + SMEM_EMB_F4 * 16 + WALK_LEN * 8);
    __shared__ int s_last;

    int b = blockIdx.x;
    int tid = threadIdx.x, lane = tid & 31, w = tid >> 5;

    if (tid < WALK_LEN) {
        int id = walks[b * WALK_LEN + tid];
        ids_s[tid] = id;
        inv_s[tid] = g_inv[id];
    }
    __syncthreads();

    for (int f = tid; f < WALK_LEN * 64; f += 512) {
        int r = f >> 6, q = f & 63;
        int id = ids_s[r];
        float iv = inv_s[r];
        uint4 raw = (q < 32) ? *(const uint4*)(g_e1h + (size_t)id * 256 + q * 8)
                             : *(const uint4*)(g_e2h + (size_t)id * 256 + (q - 32) * 8);
        float fv[8]; h8_to_f8(raw, fv);
        sm4[r * 128 + 2 * q]     = make_float4(fv[0] * iv, fv[1] * iv, fv[2] * iv, fv[3] * iv);
        sm4[r * 128 + 2 * q + 1] = make_float4(fv[4] * iv, fv[5] * iv, fv[6] * iv, fv[7] * iv);
    }
    __syncthreads();

    float term_acc = 0.f;
    for (int k = 0; k < 4; k++) {
        int l = (w << 2) | k;
        const float4* ar = sm4 + (size_t)l * 128;
        float4 A0 = ar[lane], A1 = ar[32 + lane], A2 = ar[64 + lane], A3 = ar[96 + lane];

        int posid[2 * WINDOW];
        bool pval[2 * WINDOW];
        float pos_sum = 0.f;
#pragma unroll
        for (int p = 0; p < 2 * WINDOW; p++) {
            int off = (p < WINDOW) ? (p - WINDOW) : (p - WINDOW + 1);
            int pp = l + off;
            bool val = (pp >= 0) && (pp < WALK_LEN);
            int ppc = min(max(pp, 0), WALK_LEN - 1);
            pval[p] = val;
            posid[p] = ids_s[ppc];
            const float4* pr = sm4 + (size_t)ppc * 128;
            float4 P0 = pr[lane], P1 = pr[32 + lane], P2 = pr[64 + lane], P3 = pr[96 + lane];
            float d = dot16(A0, A1, A2, A3, P0, P1, P2, P3);
            if (val) pos_sum += __expf(d * INV_TEMP);
        }

        int nbase = (b * WALK_LEN + l) * NEG_S;
        int ngl = (lane < NEG_S) ? negs[nbase + lane] : 0;
        float neg_sum = 0.f;
#pragma unroll
        for (int s = 0; s < NEG_S; s++) {
            int ng = __shfl_sync(0xffffffffu, ngl, s);
            bool inpos = false;
#pragma unroll
            for (int p = 0; p < 2 * WINDOW; p++)
                inpos = inpos || (pval[p] && (ng == posid[p]));
            const __half* n1 = g_e1h + (size_t)ng * 256;
            const __half* n2 = g_e2h + (size_t)ng * 256;
            float4 P0 = h4_to_f4(*(const uint2*)(n1 + 4 * lane));
            float4 P1 = h4_to_f4(*(const uint2*)(n1 + 128 + 4 * lane));
            float4 P2 = h4_to_f4(*(const uint2*)(n2 + 4 * lane));
            float4 P3 = h4_to_f4(*(const uint2*)(n2 + 128 + 4 * lane));
            float d = dot16(A0, A1, A2, A3, P0, P1, P2, P3);
            float sim = d * g_inv[ng] * INV_TEMP;
            if (!inpos) neg_sum += __expf(sim);
        }
        term_acc += log1pf(neg_sum / pos_sum);
    }

    if (lane == 0) wsum[w] = term_acc;
    __syncthreads();
    if (w == 0) {
        float s = (lane < 16) ? wsum[lane] : 0.f;
#pragma unroll
        for (int o = 16; o; o >>= 1) s += __shfl_xor_sync(0xffffffffu, s, o);
        if (lane == 0) g_terms[b] = s;
    }

    // last-block deterministic reduction (ticket self-resets for graph replay)
    if (tid == 0) {
        __threadfence();
        unsigned t = atomicAdd(&g_done, 1u);
        s_last = (t == NUM_WALKS - 1);
    }
    __syncthreads();
    if (s_last) {
        __threadfence();
        float v = g_terms[tid];
        __syncthreads();
        __shared__ float red[512];
        red[tid] = v;
        __syncthreads();
        for (int o = 256; o; o >>= 1) {
            if (tid < o) red[tid] += red[tid + o];
            __syncthreads();
        }
        if (tid == 0) { out[0] = red[0]; g_done = 0; }
    }
}

// ---------------- driver ---------------------------------------------------
extern "C" void kernel_launch(void* const* d_in, const int* in_sizes, int n_in,
                              void* d_out, int out_size)
{
    const float* x          = (const float*)d_in[0];
    const int*   edge_index = (const int*)  d_in[1];
    const int*   walks      = (const int*)  d_in[2];
    const int*   negs       = (const int*)  d_in[3];
    const float* W1         = (const float*)d_in[4];
    const float* a_src1     = (const float*)d_in[5];
    const float* a_dst1     = (const float*)d_in[6];
    const float* b1         = (const float*)d_in[7];
    const float* W2         = (const float*)d_in[8];
    const float* a_src2     = (const float*)d_in[9];
    const float* a_dst2     = (const float*)d_in[10];
    const float* b2         = (const float*)d_in[11];
    float* out = (float*)d_out;

    float *als1, *ald1, *als2, *ald2, *ss1, *alpS, *alpD;
    __half *xh, *w1t, *w2t, *xw1h, *xw2h, *e1h, *e2h;
    void* degp;
    cudaGetSymbolAddress((void**)&xh,   g_xh);
    cudaGetSymbolAddress((void**)&w1t,  g_w1t);
    cudaGetSymbolAddress((void**)&w2t,  g_w2t);
    cudaGetSymbolAddress((void**)&xw1h, g_xw1h);
    cudaGetSymbolAddress((void**)&xw2h, g_xw2h);
    cudaGetSymbolAddress((void**)&e1h,  g_e1h);
    cudaGetSymbolAddress((void**)&e2h,  g_e2h);
    cudaGetSymbolAddress((void**)&als1, g_als1);
    cudaGetSymbolAddress((void**)&ald1, g_ald1);
    cudaGetSymbolAddress((void**)&als2, g_als2);
    cudaGetSymbolAddress((void**)&ald2, g_ald2);
    cudaGetSymbolAddress((void**)&alpS, g_alpS);
    cudaGetSymbolAddress((void**)&alpD, g_alpD);
    cudaGetSymbolAddress((void**)&ss1,  g_ss1);
    cudaGetSymbolAddress(&degp, g_deg);

    static cudaStream_t s2 = nullptr;
    static cudaEvent_t evF = nullptr, evW = nullptr, evJ = nullptr;
    static int attr_set = 0;
    if (!attr_set) {
        cudaFuncSetAttribute(k_loss, cudaFuncAttributeMaxDynamicSharedMemorySize,
                             SMEM_LOSS_BYTES);
        cudaFuncSetAttribute(k_mmagemm<1>, cudaFuncAttributeMaxDynamicSharedMemorySize,
                             MSM_TOTAL);
        cudaFuncSetAttribute(k_mmagemm<2>, cudaFuncAttributeMaxDynamicSharedMemorySize,
                             MSM_TOTAL);
        cudaStreamCreateWithFlags(&s2, cudaStreamNonBlocking);
        cudaEventCreateWithFlags(&evF, cudaEventDisableTiming);
        cudaEventCreateWithFlags(&evW, cudaEventDisableTiming);
        cudaEventCreateWithFlags(&evJ, cudaEventDisableTiming);
        attr_set = 1;
    }

    // ---- fork: W-prep + CSR build on s2; x-prep + GEMM1 on main -----------
    cudaEventRecord(evF, 0);
    cudaStreamWaitEvent(s2, evF, 0);

    k_prepW<<<dim3(8, FIN / 32), dim3(32, 8), 0, s2>>>(W1, w1t, FIN);
    k_prepW<<<dim3(8, H1 / 32), dim3(32, 8), 0, s2>>>(W2, w2t, H1);
    cudaEventRecord(evW, s2);

    cudaMemsetAsync(degp, 0, NN * sizeof(int), s2);
    k_count<<<(EE + 255) / 256, 256, 0, s2>>>(edge_index);
    k_scan<<<1, 1024, 0, s2>>>();
    k_scatter<<<(EE + 255) / 256, 256, 0, s2>>>(edge_index);
    cudaEventRecord(evJ, s2);

    k_prepX<<<(NXCHUNK + 255) / 256, 256>>>(x);
    cudaStreamWaitEvent(0, evW, 0);
    k_mmagemm<1><<<dim3(NPAD / 128, 2), 256, MSM_TOTAL>>>(
        xh, w1t, xw1h, FIN, a_src1, a_dst1, als1, ald1);

    // ---- join CSR ----------------------------------------------------------
    cudaStreamWaitEvent(0, evJ, 0);

    // layer 1 aggregation (emb1 -> e1h, also GEMM2's A operand)
    k_agg_w<NHEADS, true, false><<<(NN * 32 + 255) / 256, 256>>>(
        xw1h, als1, ald1, b1, e1h, ss1);

    // layer 2
    k_mmagemm<2><<<dim3(NPAD / 128, 2), 256, MSM_TOTAL>>>(
        e1h, w2t, xw2h, H1, a_src2, a_dst2, alpS, alpD);
    k_alsum2<<<(NN + 255) / 256, 256>>>();
    k_agg_w<1, false, true><<<(NN * 32 + 255) / 256, 256>>>(
        xw2h, als2, ald2, b2, e2h, ss1);

    // loss (+ fused final reduction)
    k_loss<<<NUM_WALKS, 512, SMEM_LOSS_BYTES>>>(walks, negs, out);
}

// round 16
// speedup vs baseline: 1.1070x; 1.0997x over previous
#include <cuda_runtime.h>
#include <cuda_fp16.h>
#include <cstdint>

#define NN 50000
#define NPAD 50048
#define EE 800000
#define FIN 128
#define HID 32
#define NHEADS 8
#define H1 256
#define NUM_WALKS 512
#define WALK_LEN 64
#define WINDOW 5
#define NEG_S 10
#define NEG_SLOPE 0.2f
#define INV_TEMP (1.0f/0.07f)
#define SCAN_NBLK 13           // ceil(NN / 4096)

// ---------------- scratch (device globals; no cudaMalloc allowed) ----------
__device__ __half g_xh[(size_t)NPAD * FIN];
__device__ __half g_w1t[256 * FIN];
__device__ __half g_w2t[256 * H1];
__device__ __half g_xw1h[(size_t)NPAD * H1];
__device__ __half g_xw2h[(size_t)NPAD * H1];
__device__ __half g_e1h[(size_t)NPAD * H1];
__device__ __half g_e2h[(size_t)NN * H1];
__device__ float g_als1[(size_t)NPAD * NHEADS];
__device__ float g_ald1[(size_t)NPAD * NHEADS];
__device__ float g_als2[NN];
__device__ float g_ald2[NN];
__device__ float g_alpS[8 * NPAD];
__device__ float g_alpD[8 * NPAD];
__device__ float g_ss1[NN];
__device__ float g_inv[NN];
__device__ int   g_deg[NN];
__device__ int   g_rowptr[NN + 1];
__device__ int   g_wptr[NN];
__device__ int   g_col[EE];
__device__ int   g_bsum[SCAN_NBLK];
__device__ float g_terms[NUM_WALKS];
__device__ unsigned g_done;

// ---------------- PTX helpers (arch-generic sm_80+) ------------------------
__device__ __forceinline__ uint32_t smem_u32(const void* p) {
    uint32_t a;
    asm("{ .reg .u64 t; cvta.to.shared.u64 t, %1; cvt.u32.u64 %0, t; }" : "=r"(a) : "l"(p));
    return a;
}
#define CP16(SADDR, GPTR) \
    asm volatile("cp.async.cg.shared.global [%0], [%1], 16;" :: "r"(SADDR), "l"(GPTR))
#define CP_COMMIT() asm volatile("cp.async.commit_group;" ::: "memory")
#define CP_WAIT(N)  asm volatile("cp.async.wait_group %0;" :: "n"(N) : "memory")
#define LDSM4(R, ADDR) \
    asm volatile("ldmatrix.sync.aligned.m8n8.x4.shared.b16 {%0,%1,%2,%3}, [%4];" \
        : "=r"((R)[0]), "=r"((R)[1]), "=r"((R)[2]), "=r"((R)[3]) : "r"(ADDR))
#define MMAF16(C, A, B0, B1) \
    asm volatile("mma.sync.aligned.m16n8k16.row.col.f32.f16.f16.f32 " \
        "{%0,%1,%2,%3}, {%4,%5,%6,%7}, {%8,%9}, {%0,%1,%2,%3};" \
        : "+f"((C)[0]), "+f"((C)[1]), "+f"((C)[2]), "+f"((C)[3]) \
        : "r"((A)[0]), "r"((A)[1]), "r"((A)[2]), "r"((A)[3]), "r"(B0), "r"(B1))

__device__ __forceinline__ void h8_to_f8(const uint4& r, float* f) {
    const __half2* hp = reinterpret_cast<const __half2*>(&r);
#pragma unroll
    for (int i = 0; i < 4; i++) {
        float2 t = __half22float2(hp[i]);
        f[2 * i] = t.x; f[2 * i + 1] = t.y;
    }
}

// ---------------- CSR build ------------------------------------------------
__global__ void k_count(const int* __restrict__ edge_index) {
    int t = blockIdx.x * blockDim.x + threadIdx.x;
    if (t * 4 >= EE) return;
    int4 d = *(const int4*)(edge_index + EE + t * 4);
    atomicAdd(&g_deg[d.x], 1);
    atomicAdd(&g_deg[d.y], 1);
    atomicAdd(&g_deg[d.z], 1);
    atomicAdd(&g_deg[d.w], 1);
}

// phase A: per-block local exclusive scan (4096 elems/block) + block totals
__global__ __launch_bounds__(1024)
void k_scanA()
{
    __shared__ int wsums[32];
    int tid = threadIdx.x, lane = tid & 31, w = tid >> 5;
    int i0 = blockIdx.x * 4096 + tid * 4;
    int v[4];
    if (i0 + 4 <= NN) {
        int4 q = *(const int4*)(g_deg + i0);
        v[0] = q.x; v[1] = q.y; v[2] = q.z; v[3] = q.w;
    } else {
#pragma unroll
        for (int j = 0; j < 4; j++) v[j] = (i0 + j < NN) ? g_deg[i0 + j] : 0;
    }
    int tsum = v[0] + v[1] + v[2] + v[3];
    int inc = tsum;
#pragma unroll
    for (int o = 1; o < 32; o <<= 1) {
        int t2 = __shfl_up_sync(0xffffffffu, inc, o);
        if (lane >= o) inc += t2;
    }
    if (lane == 31) wsums[w] = inc;
    __syncthreads();
    if (w == 0) {
        int ws = wsums[lane];
#pragma unroll
        for (int o = 1; o < 32; o <<= 1) {
            int t2 = __shfl_up_sync(0xffffffffu, ws, o);
            if (lane >= o) ws += t2;
        }
        wsums[lane] = ws;
    }
    __syncthreads();
    int off = (w ? wsums[w - 1] : 0) + inc - tsum;   // local exclusive prefix
    int e0 = off, e1 = e0 + v[0], e2 = e1 + v[1], e3 = e2 + v[2];
    if (i0 < NN)     g_rowptr[i0]     = e0;
    if (i0 + 1 < NN) g_rowptr[i0 + 1] = e1;
    if (i0 + 2 < NN) g_rowptr[i0 + 2] = e2;
    if (i0 + 3 < NN) g_rowptr[i0 + 3] = e3;
    if (tid == 0) g_bsum[blockIdx.x] = wsums[31];
}

// phase B: add cross-block offsets, emit wptr, write rowptr[NN]
__global__ __launch_bounds__(1024)
void k_scanB()
{
    int b = blockIdx.x;
    int off = 0;
#pragma unroll
    for (int k = 0; k < SCAN_NBLK; k++) {
        int s = g_bsum[k];
        if (k < b) off += s;
    }
    int tid = threadIdx.x;
    int i0 = b * 4096 + tid * 4;
    if (i0 + 4 <= NN) {
        int4 q = *(const int4*)(g_rowptr + i0);
        q.x += off; q.y += off; q.z += off; q.w += off;
        *(int4*)(g_rowptr + i0) = q;
        *(int4*)(g_wptr + i0) = q;
    } else {
        for (int j = 0; j < 4 && i0 + j < NN; j++) {
            int v = g_rowptr[i0 + j] + off;
            g_rowptr[i0 + j] = v;
            g_wptr[i0 + j] = v;
        }
    }
    if (b == SCAN_NBLK - 1 && tid == 0) {
        int tot = off + g_bsum[SCAN_NBLK - 1];
        g_rowptr[NN] = tot;
    }
}

__global__ void k_scatter(const int* __restrict__ edge_index) {
    int e = blockIdx.x * blockDim.x + threadIdx.x;
    if (e < EE) {
        int src = edge_index[e];
        int dst = edge_index[EE + e];
        g_col[atomicAdd(&g_wptr[dst], 1)] = src;
    }
}

// ---------------- fused fp16 prep: x cvt + W1t + W2t -----------------------
#define NXCHUNK (NPAD * FIN / 4)
__global__ void k_prep(const float* __restrict__ x, const float* __restrict__ W1f,
                       const float* __restrict__ W2f)
{
    int t = blockIdx.x * blockDim.x + threadIdx.x;
    if (t < NXCHUNK) {
        int base = t * 4;
        int row = base >> 7;
        float4 v = (row < NN) ? *(const float4*)(x + base) : make_float4(0.f, 0.f, 0.f, 0.f);
        __half2 h0 = __floats2half2_rn(v.x, v.y);
        __half2 h1 = __floats2half2_rn(v.z, v.w);
        *(uint2*)(g_xh + base) = make_uint2(*(unsigned*)&h0, *(unsigned*)&h1);
    } else {
        int u = t - NXCHUNK;
        if (u < 256 * FIN) {
            int n = u / FIN, k = u - n * FIN;
            g_w1t[u] = __float2half_rn(W1f[k * 256 + n]);
        } else if (u < 256 * FIN + 256 * H1) {
            int v2 = u - 256 * FIN;
            int n = v2 / H1, k = v2 - n * H1;
            g_w2t[v2] = __float2half_rn(W2f[k * 256 + n]);
        }
    }
}

// ---------------- fp16 HMMA GEMM, fp16 C, fused al epilogue ----------------
#define MBUF 10240
#define MSTAGE (2 * MBUF)
#define MSM_TOTAL (2 * MSTAGE)

__device__ __forceinline__ void stage_chunk(
    uint32_t sb32, int rbase, int nbase, int k0, int K, int tid,
    const __half* __restrict__ A, const __half* __restrict__ B)
{
#pragma unroll
    for (int t = tid; t < 512; t += 256) {
        int r = t >> 2, seg = t & 3;
        uint32_t so = sb32 + r * 80 + seg * 16;
        CP16(so,        A + (size_t)(rbase + r) * K + k0 + seg * 8);
        CP16(so + MBUF, B + (size_t)(nbase + r) * K + k0 + seg * 8);
    }
}

template<int FOLD>
__global__ __launch_bounds__(256)
void k_mmagemm(const __half* __restrict__ A, const __half* __restrict__ B,
               __half* __restrict__ C, int K,
               const float* __restrict__ avs, const float* __restrict__ avd,
               float* __restrict__ foldS, float* __restrict__ foldD)
{
    extern __shared__ char sm[];
    uint32_t smb = smem_u32(sm);
    int tid = threadIdx.x, lane = tid & 31, wid = tid >> 5;
    int rbase = blockIdx.x * 128, nbase = blockIdx.y * 128;
    int wm = (wid >> 2) * 64, wn = (wid & 3) * 32;

    float acc[4][4][4];
#pragma unroll
    for (int i = 0; i < 4; i++)
#pragma unroll
        for (int j = 0; j < 4; j++)
#pragma unroll
            for (int q = 0; q < 4; q++) acc[i][j][q] = 0.f;

    int nch = K >> 5;
    stage_chunk(smb, rbase, nbase, 0, K, tid, A, B);
    CP_COMMIT();

    int row = lane & 15, kh = lane >> 4;
    for (int ch = 0; ch < nch; ch++) {
        if (ch + 1 < nch) {
            stage_chunk(smb + ((ch + 1) & 1) * MSTAGE, rbase, nbase, (ch + 1) << 5, K, tid, A, B);
            CP_COMMIT();
            CP_WAIT(1);
        } else {
            CP_WAIT(0);
        }
        __syncthreads();

        uint32_t s0 = smb + (ch & 1) * MSTAGE;
#pragma unroll
        for (int s = 0; s < 2; s++) {
            int colb = (s * 16 + kh * 8) * 2;
            uint32_t ah[4][4], bh[2][4];
#pragma unroll
            for (int mi = 0; mi < 4; mi++)
                LDSM4(ah[mi], s0 + (wm + mi * 16 + row) * 80 + colb);
#pragma unroll
            for (int bi = 0; bi < 2; bi++)
                LDSM4(bh[bi], s0 + MBUF + (wn + bi * 16 + row) * 80 + colb);
#pragma unroll
            for (int mi = 0; mi < 4; mi++)
#pragma unroll
                for (int ni = 0; ni < 4; ni++) {
                    int bi = ni >> 1, hf = ni & 1;
                    MMAF16(acc[mi][ni], ah[mi], bh[bi][hf], bh[bi][hf + 2]);
                }
        }
        __syncthreads();
    }

#pragma unroll
    for (int mi = 0; mi < 4; mi++)
#pragma unroll
        for (int ni = 0; ni < 4; ni++) {
            int r0 = rbase + wm + mi * 16 + (lane >> 2);
            int c  = nbase + wn + ni * 8 + (lane & 3) * 2;
            __half* p = C + (size_t)r0 * 256 + c;
            *(__half2*)p = __floats2half2_rn(acc[mi][ni][0], acc[mi][ni][1]);
            *(__half2*)(p + 8 * 256) = __floats2half2_rn(acc[mi][ni][2], acc[mi][ni][3]);
        }

    // fused attention-logit fold
    {
        int h = (nbase + wn) >> 5;
        int slot = blockIdx.y * 4 + (wid & 3);
#pragma unroll
        for (int mi = 0; mi < 4; mi++) {
            float ps0 = 0.f, ps1 = 0.f, pd0 = 0.f, pd1 = 0.f;
#pragma unroll
            for (int ni = 0; ni < 4; ni++) {
                int cc = ni * 8 + (lane & 3) * 2;
                float s0, s1, d0, d1;
                if (FOLD == 1) {
                    s0 = avs[h * 32 + cc]; s1 = avs[h * 32 + cc + 1];
                    d0 = avd[h * 32 + cc]; d1 = avd[h * 32 + cc + 1];
                } else {
                    int c = nbase + wn + cc;
                    s0 = avs[c]; s1 = avs[c + 1];
                    d0 = avd[c]; d1 = avd[c + 1];
                }
                ps0 += acc[mi][ni][0] * s0 + acc[mi][ni][1] * s1;
                ps1 += acc[mi][ni][2] * s0 + acc[mi][ni][3] * s1;
                pd0 += acc[mi][ni][0] * d0 + acc[mi][ni][1] * d1;
                pd1 += acc[mi][ni][2] * d0 + acc[mi][ni][3] * d1;
            }
#pragma unroll
            for (int o = 1; o <= 2; o <<= 1) {
                ps0 += __shfl_xor_sync(0xffffffffu, ps0, o);
                ps1 += __shfl_xor_sync(0xffffffffu, ps1, o);
                pd0 += __shfl_xor_sync(0xffffffffu, pd0, o);
                pd1 += __shfl_xor_sync(0xffffffffu, pd1, o);
            }
            if ((lane & 3) == 0) {
                int r0 = rbase + wm + mi * 16 + (lane >> 2);
                if (FOLD == 1) {
                    foldS[(size_t)r0 * 8 + h] = ps0;
                    foldS[(size_t)(r0 + 8) * 8 + h] = ps1;
                    foldD[(size_t)r0 * 8 + h] = pd0;
                    foldD[(size_t)(r0 + 8) * 8 + h] = pd1;
                } else {
                    foldS[(size_t)slot * NPAD + r0] = ps0;
                    foldS[(size_t)slot * NPAD + r0 + 8] = ps1;
                    foldD[(size_t)slot * NPAD + r0] = pd0;
                    foldD[(size_t)slot * NPAD + r0 + 8] = pd1;
                }
            }
        }
    }
}

// sum the 8 layer-2 al partial slots (deterministic)
__global__ void k_alsum2()
{
    int i = blockIdx.x * blockDim.x + threadIdx.x;
    if (i >= NN) return;
    float s = 0.f, d = 0.f;
#pragma unroll
    for (int k = 0; k < 8; k++) {
        s += g_alpS[(size_t)k * NPAD + i];
        d += g_alpD[(size_t)k * NPAD + i];
    }
    g_als2[i] = s;
    g_ald2[i] = d;
}

// ---------------- warp-per-node softmax aggregation (R10 version) ----------
template<int H, bool ELU, bool FININV>
__global__ __launch_bounds__(256)
void k_agg_w(const __half* __restrict__ xw, const float* __restrict__ als,
             const float* __restrict__ ald, const float* __restrict__ bias,
             __half* __restrict__ outh, float* __restrict__ ssout)
{
    int gw = (blockIdx.x * blockDim.x + threadIdx.x) >> 5;
    int lane = threadIdx.x & 31;
    if (gw >= NN) return;
    int n = gw;
    int beg = g_rowptr[n];
    int deg = g_rowptr[n + 1] - beg;

    const int myh = (H == 8) ? (lane >> 2) : 0;
    const float admy = ald[(size_t)n * H + myh];

    float eself = als[(size_t)n * H + myh] + admy;
    eself = eself > 0.f ? eself : NEG_SLOPE * eself;
    float exs = __expf(eself);
    float den = exs;

    float acc[8];
    {
        uint4 raw = *(const uint4*)(xw + (size_t)n * 256 + (lane << 3));
        float f[8]; h8_to_f8(raw, f);
#pragma unroll
        for (int t = 0; t < 8; t++) acc[t] = exs * f[t];
    }

    for (int base = 0; base < deg; base += 32) {
        int idx = base + lane;
        int scol = (idx < deg) ? g_col[beg + idx] : 0;
        int cn = min(32, deg - base);
#pragma unroll 4
        for (int jj = 0; jj < cn; jj++) {
            int s = __shfl_sync(0xffffffffu, scol, jj);
            float e = als[(size_t)s * H + myh] + admy;
            e = e > 0.f ? e : NEG_SLOPE * e;
            float ex = __expf(e);
            den += ex;
            uint4 raw = *(const uint4*)(xw + (size_t)s * 256 + (lane << 3));
            float f[8]; h8_to_f8(raw, f);
#pragma unroll
            for (int t = 0; t < 8; t++) acc[t] += ex * f[t];
        }
    }

    float invd = 1.f / den;
    const float4* bb = (const float4*)(bias + (lane << 3));
    float4 b0 = bb[0], b1 = bb[1];
    float o[8];
    o[0] = acc[0] * invd + b0.x; o[1] = acc[1] * invd + b0.y;
    o[2] = acc[2] * invd + b0.z; o[3] = acc[3] * invd + b0.w;
    o[4] = acc[4] * invd + b1.x; o[5] = acc[5] * invd + b1.y;
    o[6] = acc[6] * invd + b1.z; o[7] = acc[7] * invd + b1.w;
    float ssq = 0.f;
#pragma unroll
    for (int t = 0; t < 8; t++) {
        if (ELU) o[t] = o[t] > 0.f ? o[t] : expm1f(o[t]);
        ssq += o[t] * o[t];
    }
    {
        uint4 ho;
        __half2* hp = (__half2*)&ho;
        hp[0] = __floats2half2_rn(o[0], o[1]);
        hp[1] = __floats2half2_rn(o[2], o[3]);
        hp[2] = __floats2half2_rn(o[4], o[5]);
        hp[3] = __floats2half2_rn(o[6], o[7]);
        *(uint4*)(outh + (size_t)n * 256 + (lane << 3)) = ho;
    }
#pragma unroll
    for (int oo = 16; oo; oo >>= 1) ssq += __shfl_xor_sync(0xffffffffu, ssq, oo);
    if (lane == 0) {
        if (FININV) g_inv[n] = 1.f / fmaxf(sqrtf(ssout[n] + ssq), 1e-8f);
        else        ssout[n] = ssq;
    }
}

// ---------------- contrastive loss: block per walk + last-block reduce -----
#define SMEM_EMB_F4 (WALK_LEN * 128)
#define SMEM_LOSS_BYTES (SMEM_EMB_F4 * 16 + WALK_LEN * 4 + WALK_LEN * 4 + 16 * 4)

__device__ __forceinline__ float dot16(const float4& a0, const float4& a1,
                                       const float4& a2, const float4& a3,
                                       const float4& p0, const float4& p1,
                                       const float4& p2, const float4& p3)
{
    float s = a0.x * p0.x + a0.y * p0.y + a0.z * p0.z + a0.w * p0.w
            + a1.x * p1.x + a1.y * p1.y + a1.z * p1.z + a1.w * p1.w
            + a2.x * p2.x + a2.y * p2.y + a2.z * p2.z + a2.w * p2.w
            + a3.x * p3.x + a3.y * p3.y + a3.z * p3.z + a3.w * p3.w;
#pragma unroll
    for (int o = 16; o; o >>= 1) s += __shfl_xor_sync(0xffffffffu, s, o);
    return s;
}
__device__ __forceinline__ float4 h4_to_f4(uint2 r) {
    const __half2* hp = reinterpret_cast<const __half2*>(&r);
    float2 a = __half22float2(hp[0]), b = __half22float2(hp[1]);
    return make_float4(a.x, a.y, b.x, b.y);
}

__global__ __launch_bounds__(512)
void k_loss(const int* __restrict__ walks, const int* __restrict__ negs,
            float* __restrict__ out)
{
    extern __shared__ char smraw[];
    float4* sm4   = (float4*)smraw;
    int*    ids_s = (int*)(smraw + SMEM_EMB_F4 * 16);
    float*  inv_s = (float*)(smraw + SMEM_EMB_F4 * 16 + WALK_LEN * 4);
    float*  wsum  = (float*)(smraw + SMEM_EMB_F4 * 16 + WALK_LEN * 8);
    __shared__ int s_last;

    int b = blockIdx.x;
    int tid = threadIdx.x, lane = tid & 31, w = tid >> 5;

    if (tid < WALK_LEN) {
        int id = walks[b * WALK_LEN + tid];
        ids_s[tid] = id;
        inv_s[tid] = g_inv[id];
    }
    __syncthreads();

    for (int f = tid; f < WALK_LEN * 64; f += 512) {
        int r = f >> 6, q = f & 63;
        int id = ids_s[r];
        float iv = inv_s[r];
        uint4 raw = (q < 32) ? *(const uint4*)(g_e1h + (size_t)id * 256 + q * 8)
                             : *(const uint4*)(g_e2h + (size_t)id * 256 + (q - 32) * 8);
        float fv[8]; h8_to_f8(raw, fv);
        sm4[r * 128 + 2 * q]     = make_float4(fv[0] * iv, fv[1] * iv, fv[2] * iv, fv[3] * iv);
        sm4[r * 128 + 2 * q + 1] = make_float4(fv[4] * iv, fv[5] * iv, fv[6] * iv, fv[7] * iv);
    }
    __syncthreads();

    float term_acc = 0.f;
    for (int k = 0; k < 4; k++) {
        int l = (w << 2) | k;
        const float4* ar = sm4 + (size_t)l * 128;
        float4 A0 = ar[lane], A1 = ar[32 + lane], A2 = ar[64 + lane], A3 = ar[96 + lane];

        int posid[2 * WINDOW];
        bool pval[2 * WINDOW];
        float pos_sum = 0.f;
#pragma unroll
        for (int p = 0; p < 2 * WINDOW; p++) {
            int off = (p < WINDOW) ? (p - WINDOW) : (p - WINDOW + 1);
            int pp = l + off;
            bool val = (pp >= 0) && (pp < WALK_LEN);
            int ppc = min(max(pp, 0), WALK_LEN - 1);
            pval[p] = val;
            posid[p] = ids_s[ppc];
            const float4* pr = sm4 + (size_t)ppc * 128;
            float4 P0 = pr[lane], P1 = pr[32 + lane], P2 = pr[64 + lane], P3 = pr[96 + lane];
            float d = dot16(A0, A1, A2, A3, P0, P1, P2, P3);
            if (val) pos_sum += __expf(d * INV_TEMP);
        }

        int nbase = (b * WALK_LEN + l) * NEG_S;
        int ngl = (lane < NEG_S) ? negs[nbase + lane] : 0;
        float neg_sum = 0.f;
#pragma unroll
        for (int s = 0; s < NEG_S; s++) {
            int ng = __shfl_sync(0xffffffffu, ngl, s);
            bool inpos = false;
#pragma unroll
            for (int p = 0; p < 2 * WINDOW; p++)
                inpos = inpos || (pval[p] && (ng == posid[p]));
            const __half* n1 = g_e1h + (size_t)ng * 256;
            const __half* n2 = g_e2h + (size_t)ng * 256;
            float4 P0 = h4_to_f4(*(const uint2*)(n1 + 4 * lane));
            float4 P1 = h4_to_f4(*(const uint2*)(n1 + 128 + 4 * lane));
            float4 P2 = h4_to_f4(*(const uint2*)(n2 + 4 * lane));
            float4 P3 = h4_to_f4(*(const uint2*)(n2 + 128 + 4 * lane));
            float d = dot16(A0, A1, A2, A3, P0, P1, P2, P3);
            float sim = d * g_inv[ng] * INV_TEMP;
            if (!inpos) neg_sum += __expf(sim);
        }
        term_acc += log1pf(neg_sum / pos_sum);
    }

    if (lane == 0) wsum[w] = term_acc;
    __syncthreads();
    if (w == 0) {
        float s = (lane < 16) ? wsum[lane] : 0.f;
#pragma unroll
        for (int o = 16; o; o >>= 1) s += __shfl_xor_sync(0xffffffffu, s, o);
        if (lane == 0) g_terms[b] = s;
    }

    // last-block deterministic reduction (ticket self-resets for graph replay)
    if (tid == 0) {
        __threadfence();
        unsigned t = atomicAdd(&g_done, 1u);
        s_last = (t == NUM_WALKS - 1);
    }
    __syncthreads();
    if (s_last) {
        __threadfence();
        float v = g_terms[tid];
        __syncthreads();
        __shared__ float red[512];
        red[tid] = v;
        __syncthreads();
        for (int o = 256; o; o >>= 1) {
            if (tid < o) red[tid] += red[tid + o];
            __syncthreads();
        }
        if (tid == 0) { out[0] = red[0]; g_done = 0; }
    }
}

// ---------------- driver ---------------------------------------------------
extern "C" void kernel_launch(void* const* d_in, const int* in_sizes, int n_in,
                              void* d_out, int out_size)
{
    const float* x          = (const float*)d_in[0];
    const int*   edge_index = (const int*)  d_in[1];
    const int*   walks      = (const int*)  d_in[2];
    const int*   negs       = (const int*)  d_in[3];
    const float* W1         = (const float*)d_in[4];
    const float* a_src1     = (const float*)d_in[5];
    const float* a_dst1     = (const float*)d_in[6];
    const float* b1         = (const float*)d_in[7];
    const float* W2         = (const float*)d_in[8];
    const float* a_src2     = (const float*)d_in[9];
    const float* a_dst2     = (const float*)d_in[10];
    const float* b2         = (const float*)d_in[11];
    float* out = (float*)d_out;

    float *als1, *ald1, *als2, *ald2, *ss1, *alpS, *alpD;
    __half *xh, *w1t, *w2t, *xw1h, *xw2h, *e1h, *e2h;
    void* degp;
    cudaGetSymbolAddress((void**)&xh,   g_xh);
    cudaGetSymbolAddress((void**)&w1t,  g_w1t);
    cudaGetSymbolAddress((void**)&w2t,  g_w2t);
    cudaGetSymbolAddress((void**)&xw1h, g_xw1h);
    cudaGetSymbolAddress((void**)&xw2h, g_xw2h);
    cudaGetSymbolAddress((void**)&e1h,  g_e1h);
    cudaGetSymbolAddress((void**)&e2h,  g_e2h);
    cudaGetSymbolAddress((void**)&als1, g_als1);
    cudaGetSymbolAddress((void**)&ald1, g_ald1);
    cudaGetSymbolAddress((void**)&als2, g_als2);
    cudaGetSymbolAddress((void**)&ald2, g_ald2);
    cudaGetSymbolAddress((void**)&alpS, g_alpS);
    cudaGetSymbolAddress((void**)&alpD, g_alpD);
    cudaGetSymbolAddress((void**)&ss1,  g_ss1);
    cudaGetSymbolAddress(&degp, g_deg);

    static cudaStream_t s2 = nullptr;
    static cudaEvent_t evF = nullptr, evJ = nullptr;
    static int attr_set = 0;
    if (!attr_set) {
        cudaFuncSetAttribute(k_loss, cudaFuncAttributeMaxDynamicSharedMemorySize,
                             SMEM_LOSS_BYTES);
        cudaFuncSetAttribute(k_mmagemm<1>, cudaFuncAttributeMaxDynamicSharedMemorySize,
                             MSM_TOTAL);
        cudaFuncSetAttribute(k_mmagemm<2>, cudaFuncAttributeMaxDynamicSharedMemorySize,
                             MSM_TOTAL);
        cudaStreamCreateWithFlags(&s2, cudaStreamNonBlocking);
        cudaEventCreateWithFlags(&evF, cudaEventDisableTiming);
        cudaEventCreateWithFlags(&evJ, cudaEventDisableTiming);
        attr_set = 1;
    }

    // ---- fork: CSR build on s2, prep + GEMM1 on main stream ---------------
    cudaEventRecord(evF, 0);
    cudaStreamWaitEvent(s2, evF, 0);

    cudaMemsetAsync(degp, 0, NN * sizeof(int), s2);
    k_count<<<(EE / 4 + 255) / 256, 256, 0, s2>>>(edge_index);
    k_scanA<<<SCAN_NBLK, 1024, 0, s2>>>();
    k_scanB<<<SCAN_NBLK, 1024, 0, s2>>>();
    k_scatter<<<(EE + 255) / 256, 256, 0, s2>>>(edge_index);
    cudaEventRecord(evJ, s2);

    k_prep<<<(NXCHUNK + 256 * (FIN + H1) + 255) / 256, 256>>>(x, W1, W2);
    k_mmagemm<1><<<dim3(NPAD / 128, 2), 256, MSM_TOTAL>>>(
        xh, w1t, xw1h, FIN, a_src1, a_dst1, als1, ald1);

    // ---- join --------------------------------------------------------------
    cudaStreamWaitEvent(0, evJ, 0);

    // layer 1 aggregation (emb1 -> e1h, also GEMM2's A operand)
    k_agg_w<NHEADS, true, false><<<(NN * 32 + 255) / 256, 256>>>(
        xw1h, als1, ald1, b1, e1h, ss1);

    // layer 2
    k_mmagemm<2><<<dim3(NPAD / 128, 2), 256, MSM_TOTAL>>>(
        e1h, w2t, xw2h, H1, a_src2, a_dst2, alpS, alpD);
    k_alsum2<<<(NN + 255) / 256, 256>>>();
    k_agg_w<1, false, true><<<(NN * 32 + 255) / 256, 256>>>(
        xw2h, als2, ald2, b2, e2h, ss1);

    // loss (+ fused final reduction)
    k_loss<<<NUM_WALKS, 512, SMEM_LOSS_BYTES>>>(walks, negs, out);
}